// round 6
// baseline (speedup 1.0000x reference)
#include <cuda_runtime.h>
#include <math.h>

// ---------------------------------------------------------------------------
// Problem constants (fixed shapes)
// ---------------------------------------------------------------------------
#define Bc   4
#define Hc   8
#define SQc  2048
#define SKc  512
#define DMc  4096
#define DKc  512

// ---------------------------------------------------------------------------
// Scratch (device globals — allocation-free kernel_launch).
// buf1: q [b,h,sq,dk]  -> later im_attn [b,h,sq,dk]      (33.5M floats)
// buf2: p_attn [b,h,sq,sk] -> later x [b,sq,h*dk]        (33.5M floats)
// ---------------------------------------------------------------------------
__device__ float g_buf1[(size_t)Bc * Hc * SQc * DKc];
__device__ float g_buf2[(size_t)Bc * Hc * SQc * SKc];
__device__ float g_k   [(size_t)Bc * Hc * SKc * DKc];   // k  [b,h,sk,dk]
__device__ float g_vt  [(size_t)Bc * Hc * DKc * SKc];   // v^T [b,h,dk,sk]
__device__ float g_imft[(size_t)Bc * Hc * DKc * SKc];   // imf^T [b,h,dk,sk]

// ---------------------------------------------------------------------------
// SGEMM (NT: C[m,n] = sum_k A[m,k] * B[n,k]), fp32, 128x128x16 tile,
// 256 threads, 8x8 per thread (split 4+4 for conflict-free LDS.128).
// MODE 0: plain row-major + bias                  (output projection)
// MODE 1: split-head [b,h,s,dk] + bias            (q, k projections)
// MODE 2: split-head transposed [b,h,dk,s] + bias (v, imf projections)
// MODE 3: batched plain (z = b*H+h), * scale      (scores / p@imf)
// MODE 4: batched merge-head [b,sq,h*dk]          (im_attn @ v)
// ---------------------------------------------------------------------------
#define BM 128
#define BN 128
#define BK 16
#define PAD 4

template <int MODE, int S>
__global__ void __launch_bounds__(256, 2)
gemm_nt(const float* __restrict__ A, const float* __restrict__ Bm,
        const float* __restrict__ bias, float* __restrict__ C,
        int M, int N, int K,
        long long sA, long long sB, long long sC, float scale)
{
    __shared__ float As[BK][BM + PAD];
    __shared__ float Bs[BK][BN + PAD];

    const int tid = threadIdx.x;
    const int tx  = tid & 15;   // 0..15  (N dir)
    const int ty  = tid >> 4;   // 0..15  (M dir)
    const int m0  = blockIdx.y * BM;
    const int n0  = blockIdx.x * BN;

    const float* Ab = A  + (long long)blockIdx.z * sA;
    const float* Bb = Bm + (long long)blockIdx.z * sB;

    const int lrow = tid >> 2;        // 0..63
    const int lcol = (tid & 3) << 2;  // 0,4,8,12

    float acc[8][8];
#pragma unroll
    for (int i = 0; i < 8; i++)
#pragma unroll
        for (int j = 0; j < 8; j++) acc[i][j] = 0.f;

    for (int k0 = 0; k0 < K; k0 += BK) {
#pragma unroll
        for (int t = 0; t < 2; t++) {
            const int r = lrow + t * 64;
            float4 av = *(const float4*)(Ab + (long long)(m0 + r) * K + k0 + lcol);
            As[lcol + 0][r] = av.x; As[lcol + 1][r] = av.y;
            As[lcol + 2][r] = av.z; As[lcol + 3][r] = av.w;
            float4 bv = *(const float4*)(Bb + (long long)(n0 + r) * K + k0 + lcol);
            Bs[lcol + 0][r] = bv.x; Bs[lcol + 1][r] = bv.y;
            Bs[lcol + 2][r] = bv.z; Bs[lcol + 3][r] = bv.w;
        }
        __syncthreads();

#pragma unroll
        for (int kk = 0; kk < BK; kk++) {
            float a[8], b[8];
            float4 a0 = *(const float4*)&As[kk][ty * 4];
            float4 a1 = *(const float4*)&As[kk][64 + ty * 4];
            a[0] = a0.x; a[1] = a0.y; a[2] = a0.z; a[3] = a0.w;
            a[4] = a1.x; a[5] = a1.y; a[6] = a1.z; a[7] = a1.w;
            float4 b0v = *(const float4*)&Bs[kk][tx * 4];
            float4 b1v = *(const float4*)&Bs[kk][64 + tx * 4];
            b[0] = b0v.x; b[1] = b0v.y; b[2] = b0v.z; b[3] = b0v.w;
            b[4] = b1v.x; b[5] = b1v.y; b[6] = b1v.z; b[7] = b1v.w;
#pragma unroll
            for (int i = 0; i < 8; i++)
#pragma unroll
                for (int j = 0; j < 8; j++)
                    acc[i][j] = fmaf(a[i], b[j], acc[i][j]);
        }
        __syncthreads();
    }

    // --- epilogue: per-thread 8x8, split 4+4 row/col mapping ---
    int rows[8], cols[8];
#pragma unroll
    for (int i = 0; i < 4; i++) {
        rows[i]     = m0 + ty * 4 + i;
        rows[i + 4] = m0 + 64 + ty * 4 + i;
        cols[i]     = n0 + tx * 4 + i;
        cols[i + 4] = n0 + 64 + tx * 4 + i;
    }

    if (MODE == 0) {
#pragma unroll
        for (int i = 0; i < 8; i++) {
            const long long ro = (long long)rows[i] * N;
#pragma unroll
            for (int j = 0; j < 8; j++)
                C[ro + cols[j]] = acc[i][j] + bias[cols[j]];
        }
    } else if (MODE == 1) {
#pragma unroll
        for (int i = 0; i < 8; i++) {
            const int r = rows[i];
            const int bb = r / S, s = r % S;
#pragma unroll
            for (int j = 0; j < 8; j++) {
                const int c = cols[j];
                const int h = c >> 9, dk = c & 511;
                C[(((long long)(bb * Hc + h) * S + s) << 9) + dk] = acc[i][j] + bias[c];
            }
        }
    } else if (MODE == 2) {
#pragma unroll
        for (int i = 0; i < 8; i++) {
            const int r = rows[i];
            const int bb = r / S, s = r % S;
#pragma unroll
            for (int j = 0; j < 8; j++) {
                const int c = cols[j];
                const int h = c >> 9, dk = c & 511;
                C[((long long)(bb * Hc + h) * DKc + dk) * S + s] = acc[i][j] + bias[c];
            }
        }
    } else if (MODE == 3) {
        float* Cb = C + (long long)blockIdx.z * sC;
#pragma unroll
        for (int i = 0; i < 8; i++) {
            const long long ro = (long long)rows[i] * N;
#pragma unroll
            for (int j = 0; j < 8; j++)
                Cb[ro + cols[j]] = acc[i][j] * scale;
        }
    } else {  // MODE 4: merge heads -> [b, sq, h*dk]
        const int z = blockIdx.z;
        const int bb = z >> 3, h = z & 7;
#pragma unroll
        for (int i = 0; i < 8; i++) {
            const long long ro = ((long long)(bb * SQc + rows[i])) * DMc + h * DKc;
#pragma unroll
            for (int j = 0; j < 8; j++)
                C[ro + cols[j]] = acc[i][j];
        }
    }
}

// ---------------------------------------------------------------------------
// Row softmax, row length 512. One warp per row, 16 elems/lane in registers.
// ---------------------------------------------------------------------------
__global__ void softmax512(float* __restrict__ data, int nrows)
{
    const int warp = (blockIdx.x * blockDim.x + threadIdx.x) >> 5;
    const int lane = threadIdx.x & 31;
    if (warp >= nrows) return;
    float* row = data + (long long)warp * 512;

    float v[16];
    float mx = -3.4e38f;
#pragma unroll
    for (int i = 0; i < 16; i++) {
        v[i] = row[lane + i * 32];
        mx = fmaxf(mx, v[i]);
    }
#pragma unroll
    for (int o = 16; o > 0; o >>= 1)
        mx = fmaxf(mx, __shfl_xor_sync(0xffffffffu, mx, o));

    float sum = 0.f;
#pragma unroll
    for (int i = 0; i < 16; i++) {
        v[i] = __expf(v[i] - mx);
        sum += v[i];
    }
#pragma unroll
    for (int o = 16; o > 0; o >>= 1)
        sum += __shfl_xor_sync(0xffffffffu, sum, o);

    const float inv = 1.0f / sum;
#pragma unroll
    for (int i = 0; i < 16; i++)
        row[lane + i * 32] = v[i] * inv;
}

// ---------------------------------------------------------------------------
// Launch: 6 GEMMs + 2 softmaxes, all on the default stream (graph-capturable,
// allocation-free; scratch lives in __device__ globals).
// ---------------------------------------------------------------------------
extern "C" void kernel_launch(void* const* d_in, const int* in_sizes, int n_in,
                              void* d_out, int out_size)
{
    const float* query = (const float*)d_in[0];
    const float* key   = (const float*)d_in[1];
    const float* value = (const float*)d_in[2];
    const float* imfe  = (const float*)d_in[3];
    const float* W0 = (const float*)d_in[4];  const float* b0 = (const float*)d_in[5];
    const float* W1 = (const float*)d_in[6];  const float* b1 = (const float*)d_in[7];
    const float* W2 = (const float*)d_in[8];  const float* b2 = (const float*)d_in[9];
    const float* W3 = (const float*)d_in[10]; const float* b3 = (const float*)d_in[11];
    float* out = (float*)d_out;

    float *buf1, *buf2, *kb, *vt, *imft;
    cudaGetSymbolAddress((void**)&buf1, g_buf1);
    cudaGetSymbolAddress((void**)&buf2, g_buf2);
    cudaGetSymbolAddress((void**)&kb,   g_k);
    cudaGetSymbolAddress((void**)&vt,   g_vt);
    cudaGetSymbolAddress((void**)&imft, g_imft);

    const dim3 blk(256);
    const float scl = 1.0f / sqrtf((float)DKc);

    // --- projections ---
    // q = split_heads(query @ W0^T + b0) -> buf1 [b,h,sq,dk]
    gemm_nt<1, SQc><<<dim3(DMc / BN, (Bc * SQc) / BM, 1), blk>>>(
        query, W0, b0, buf1, Bc * SQc, DMc, DMc, 0, 0, 0, 1.f);
    // k -> g_k [b,h,sk,dk]
    gemm_nt<1, SKc><<<dim3(DMc / BN, (Bc * SKc) / BM, 1), blk>>>(
        key, W1, b1, kb, Bc * SKc, DMc, DMc, 0, 0, 0, 1.f);
    // v -> g_vt [b,h,dk,sk] (transposed for second-stage NT contraction)
    gemm_nt<2, SKc><<<dim3(DMc / BN, (Bc * SKc) / BM, 1), blk>>>(
        value, W2, b2, vt, Bc * SKc, DMc, DMc, 0, 0, 0, 1.f);
    // imf -> g_imft [b,h,dk,sk] (transposed)
    gemm_nt<2, SKc><<<dim3(DMc / BN, (Bc * SKc) / BM, 1), blk>>>(
        imfe, W3, b3, imft, Bc * SKc, DMc, DMc, 0, 0, 0, 1.f);

    // --- scores = q @ k^T / sqrt(dk), then softmax over sk -> buf2 ---
    gemm_nt<3, 0><<<dim3(SKc / BN, SQc / BM, Bc * Hc), blk>>>(
        buf1, kb, nullptr, buf2, SQc, SKc, DKc,
        (long long)SQc * DKc, (long long)SKc * DKc, (long long)SQc * SKc, scl);
    softmax512<<<(Bc * Hc * SQc) / 8, 256>>>(buf2, Bc * Hc * SQc);

    // --- t = p_attn @ imf, softmax over d -> im_attn in buf1 (q is dead) ---
    gemm_nt<3, 0><<<dim3(DKc / BN, SQc / BM, Bc * Hc), blk>>>(
        buf2, imft, nullptr, buf1, SQc, DKc, SKc,
        (long long)SQc * SKc, (long long)DKc * SKc, (long long)SQc * DKc, 1.f);
    softmax512<<<(Bc * Hc * SQc) / 8, 256>>>(buf1, Bc * Hc * SQc);

    // --- x = im_attn @ v -> merged heads in buf2 (p_attn is dead) ---
    gemm_nt<4, 0><<<dim3(DKc / BN, SQc / BM, Bc * Hc), blk>>>(
        buf1, vt, nullptr, buf2, SQc, DKc, DKc,
        (long long)SQc * DKc, (long long)DKc * SKc, 0, 1.f);

    // --- out = x @ W3^T + b3 ---
    gemm_nt<0, 0><<<dim3(DMc / BN, (Bc * SQc) / BM, 1), blk>>>(
        buf2, W3, b3, out, Bc * SQc, DMc, DMc, 0, 0, 0, 1.f);
}